// round 4
// baseline (speedup 1.0000x reference)
#include <cuda_runtime.h>
#include <cuda_bf16.h>

// MorletTransform via per-harmonic Goertzel recurrence (f32x2 packed lanes).
// Mapping: 512 threads = 16 warps. Warp w owns harmonics 4w+1..4w+4:
//   lane l: pair-half h = l>>4 (harmonics 4w+2h+1, 4w+2h+2 in f32x2 lanes),
//           segment   s = l&15 (samples [s*64, s*64+64)).
// Segment partials are combined with 4 shfl.bfly steps (no shared round-trip).

#define TWO_PI_F 6.28318530717958647692f

__device__ __forceinline__ unsigned long long fma2(unsigned long long a,
                                                   unsigned long long b,
                                                   unsigned long long c) {
    unsigned long long d;
    asm("fma.rn.f32x2 %0, %1, %2, %3;" : "=l"(d) : "l"(a), "l"(b), "l"(c));
    return d;
}
__device__ __forceinline__ unsigned long long pk(float lo, float hi) {
    unsigned long long d;
    asm("mov.b64 %0, {%1, %2};" : "=l"(d) : "f"(lo), "f"(hi));
    return d;
}
__device__ __forceinline__ void upk(unsigned long long v, float& lo, float& hi) {
    asm("mov.b64 {%0, %1}, %2;" : "=f"(lo), "=f"(hi) : "l"(v));
}

// 16 segments, each 64 samples duplicated as (w,w) u64 + 2 u64 pad (bank skew)
#define SEG_STRIDE 66

__global__ void __launch_bounds__(512, 4)
morlet_kernel(const float* __restrict__ audio,
              const float* __restrict__ f0,
              float* __restrict__ out_hd,
              float* __restrict__ out_amp) {
    const int f   = blockIdx.x;
    const int tid = threadIdx.x;
    const int w   = tid >> 5;
    const int l   = tid & 31;

    __shared__ __align__(16) unsigned long long w2[16 * SEG_STRIDE];
    __shared__ float sMag[64];
    __shared__ float sAmp[2];

    // normalizer = 1/sqrt(pi*tp), tp = sr/half_bw = 16000
    const float normalizer = rsqrtf(3.14159265358979f * 16000.0f);
    const float inv_tp     = 1.0f / 16000.0f;
    const float inv_sr     = 1.0f / 16000.0f;
    const float f0v        = f0[f];

    // --- windowed frame: thread handles samples 2*tid, 2*tid+1 ---
    {
        float2 a = ((const float2*)audio)[(size_t)f * 512 + tid];
        int n = tid * 2;
        float d0 = (float)(n - 512);
        float d1 = (float)(n + 1 - 512);
        float w0 = a.x * (normalizer * __expf(-d0 * d0 * inv_tp));
        float w1 = a.y * (normalizer * __expf(-d1 * d1 * inv_tp));
        // segment = tid>>5 = w ; offset within segment = 2*l
        *((ulonglong2*)(w2 + w * SEG_STRIDE + 2 * l)) =
            make_ulonglong2(pk(w0, w0), pk(w1, w1));
    }

    // --- per-warp coefficients: lanes 0..3 compute accurate sincos for
    //     k = 4w+1+l  (accurate: cos error is amplified by 1/sin(theta) ~51
    //     at k=1, so __sincosf is not safe for the recurrence coefficient) ---
    float cv = 0.0f, sv = 0.0f;
    if (l < 4) {
        float fc = f0v * (float)(4 * w + l + 1) * inv_sr;
        sincosf(TWO_PI_F * fc, &sv, &cv);
    }
    const int h = l >> 4;  // pair-half
    float cA = __shfl_sync(0xffffffffu, cv, 2 * h);
    float cB = __shfl_sync(0xffffffffu, cv, 2 * h + 1);
    float sA = __shfl_sync(0xffffffffu, sv, 2 * h);
    float sB = __shfl_sync(0xffffffffu, sv, 2 * h + 1);
    const unsigned long long C2   = pk(2.0f * cA, 2.0f * cB);
    const unsigned long long NEG1 = pk(-1.0f, -1.0f);

    __syncthreads();

    // --- Goertzel over this lane's 64-sample segment, both harmonic lanes ---
    const int seg = l & 15;
    const ulonglong2* wq = (const ulonglong2*)(w2 + seg * SEG_STRIDE);

    unsigned long long s1 = 0ull, s2 = 0ull;
    #pragma unroll
    for (int m = 0; m < 32; ++m) {
        ulonglong2 q = wq[m];                         // 2 samples, duplicated
        unsigned long long t0 = fma2(NEG1, s2, q.x);  // w - s_{n-2}
        unsigned long long s0 = fma2(C2, s1, t0);
        unsigned long long t1 = fma2(NEG1, s1, q.y);
        unsigned long long sn = fma2(C2, s0, t1);
        s2 = s0;
        s1 = sn;
    }

    // --- finalize: rotate segment result to global sample index ---
    float s1A, s1B, s2A, s2B;
    upk(s1, s1A, s1B);
    upk(s2, s2A, s2B);
    const int   kA   = 4 * w + 2 * h + 1;
    const float fcA  = f0v * (float)kA * inv_sr;
    const float fcB  = f0v * (float)(kA + 1) * inv_sr;
    const float nend = (float)(seg * 64 + 63);

    float reA, imA, reB, imB;
    {
        float yre = fmaf(-cA, s2A, s1A);
        float yim = sA * s2A;
        float p   = fcA * nend;
        p -= floorf(p);
        float sphi, cphi;
        __sincosf(TWO_PI_F * p, &sphi, &cphi);
        reA = yre * cphi + yim * sphi;
        imA = yim * cphi - yre * sphi;
    }
    {
        float yre = fmaf(-cB, s2B, s1B);
        float yim = sB * s2B;
        float p   = fcB * nend;
        p -= floorf(p);
        float sphi, cphi;
        __sincosf(TWO_PI_F * p, &sphi, &cphi);
        reB = yre * cphi + yim * sphi;
        imB = yim * cphi - yre * sphi;
    }

    // --- combine 16 segments: butterfly within each 16-lane half ---
    #pragma unroll
    for (int o = 1; o < 16; o <<= 1) {
        reA += __shfl_xor_sync(0xffffffffu, reA, o);
        imA += __shfl_xor_sync(0xffffffffu, imA, o);
        reB += __shfl_xor_sync(0xffffffffu, reB, o);
        imB += __shfl_xor_sync(0xffffffffu, imB, o);
    }

    if (seg == 0) {  // lanes 0 and 16
        float magA = sqrtf(reA * reA + imA * imA);
        float magB = sqrtf(reB * reB + imB * imB);
        if (fcA > 0.5f) magA = 0.0f;  // Nyquist mask
        if (fcB > 0.5f) magB = 0.0f;
        sMag[kA - 1] = magA;
        sMag[kA]     = magB;
    }
    __syncthreads();

    // --- cross-harmonic sum + outputs ---
    if (tid < 64) {
        float mag = sMag[tid];
        float s = mag;
        #pragma unroll
        for (int o = 16; o > 0; o >>= 1)
            s += __shfl_xor_sync(0xffffffffu, s, o);
        if ((tid & 31) == 0) sAmp[tid >> 5] = s;
    }
    __syncthreads();

    if (tid < 64) {
        float amp = sAmp[0] + sAmp[1];
        out_hd[f * 64 + tid] = sMag[tid] / amp;
        if (tid == 0)
            out_amp[f] = fminf(fmaxf(amp * 2.0f, 0.0f), 1.0f);
    }
}

extern "C" void kernel_launch(void* const* d_in, const int* in_sizes, int n_in,
                              void* d_out, int out_size) {
    const float* audio = (const float*)d_in[0];
    const float* f0    = (const float*)d_in[1];
    const int frames   = in_sizes[1];  // 2*250*1 = 500
    float* out         = (float*)d_out;
    morlet_kernel<<<frames, 512>>>(audio, f0, out, out + (size_t)frames * 64);
}

// round 5
// speedup vs baseline: 1.1410x; 1.1410x over previous
#include <cuda_runtime.h>
#include <cuda_bf16.h>

// MorletTransform via per-harmonic Goertzel recurrence (f32x2 packed lanes).
// Mapping: 256 threads. Thread: pair = tid&31 (harmonics 2p+1, 2p+2 in f32x2
// lanes), segpair = tid>>5 -> runs TWO independent 64-sample Goertzel chains
// (segments 2sp, 2sp+1) for ILP. All loop LDS are warp-broadcast (all lanes
// of a warp read the same sample) -> conflict-free.
// Tail: one float2 partial per thread -> [8][64] shared -> single-warp finish.

#define TWO_PI_F 6.28318530717958647692f

__device__ __forceinline__ unsigned long long fma2(unsigned long long a,
                                                   unsigned long long b,
                                                   unsigned long long c) {
    unsigned long long d;
    asm("fma.rn.f32x2 %0, %1, %2, %3;" : "=l"(d) : "l"(a), "l"(b), "l"(c));
    return d;
}
__device__ __forceinline__ unsigned long long pk(float lo, float hi) {
    unsigned long long d;
    asm("mov.b64 %0, {%1, %2};" : "=l"(d) : "f"(lo), "f"(hi));
    return d;
}
__device__ __forceinline__ void upk(unsigned long long v, float& lo, float& hi) {
    asm("mov.b64 {%0, %1}, %2;" : "=f"(lo), "=f"(hi) : "l"(v));
}

__global__ void __launch_bounds__(256)
morlet_kernel(const float* __restrict__ audio,
              const float* __restrict__ f0,
              float* __restrict__ out_hd,
              float* __restrict__ out_amp) {
    const int f   = blockIdx.x;
    const int tid = threadIdx.x;

    __shared__ __align__(16) unsigned long long w2[1024]; // sample n -> (w[n], w[n])
    __shared__ __align__(8) float sCth[64];
    __shared__ __align__(8) float sSth[64];
    __shared__ float2 sPart[8 * 64];                      // [segpair][harmonic] (re,im)

    // normalizer = 1/sqrt(pi*tp), tp = sr/half_bw = 16000
    const float normalizer = rsqrtf(3.14159265358979f * 16000.0f);
    const float inv_tp     = 1.0f / 16000.0f;
    const float inv_sr     = 1.0f / 16000.0f;
    const float f0v        = f0[f];

    // --- windowed frame: thread handles samples 4*tid .. 4*tid+3 ---
    {
        float4 a = ((const float4*)audio)[(size_t)f * 256 + tid];
        int n = tid * 4;
        float v[4] = {a.x, a.y, a.z, a.w};
        unsigned long long o[4];
        #pragma unroll
        for (int i = 0; i < 4; ++i) {
            float d  = (float)(n + i - 512);
            float wv = v[i] * (normalizer * __expf(-d * d * inv_tp));
            o[i] = pk(wv, wv);
        }
        ((ulonglong2*)w2)[tid * 2]     = make_ulonglong2(o[0], o[1]);
        ((ulonglong2*)w2)[tid * 2 + 1] = make_ulonglong2(o[2], o[3]);
    }

    // --- per-harmonic recurrence coefficients, once (accurate: cos error is
    //     amplified by 1/sin(theta) ~51 at k=1 -> __sincosf unsafe here) ---
    if (tid < 64) {
        float fc = f0v * (float)(tid + 1) * inv_sr;
        float s, c;
        sincosf(TWO_PI_F * fc, &s, &c);
        sCth[tid] = c;
        sSth[tid] = s;
    }
    __syncthreads();

    const int pair = tid & 31;   // harmonics 2p+1, 2p+2
    const int sp   = tid >> 5;   // segment pair: segments 2sp, 2sp+1

    float2 cth = ((const float2*)sCth)[pair];
    float2 sth = ((const float2*)sSth)[pair];
    const unsigned long long C2   = pk(2.0f * cth.x, 2.0f * cth.y);
    const unsigned long long NEG1 = pk(-1.0f, -1.0f);

    // --- two interleaved 64-sample Goertzel chains (ILP=2) ---
    const ulonglong2* wq0 = (const ulonglong2*)(w2 + (2 * sp) * 64);
    const ulonglong2* wq1 = (const ulonglong2*)(w2 + (2 * sp + 1) * 64);

    unsigned long long a1 = 0ull, a2 = 0ull;  // chain A (segment 2sp)
    unsigned long long b1 = 0ull, b2 = 0ull;  // chain B (segment 2sp+1)
    #pragma unroll 8
    for (int m = 0; m < 32; ++m) {
        ulonglong2 q = wq0[m];                        // broadcast LDS.128
        ulonglong2 r = wq1[m];
        unsigned long long t0 = fma2(NEG1, a2, q.x);
        unsigned long long s0 = fma2(C2, a1, t0);
        unsigned long long t1 = fma2(NEG1, a1, q.y);
        unsigned long long sn = fma2(C2, s0, t1);
        a2 = s0; a1 = sn;
        unsigned long long u0 = fma2(NEG1, b2, r.x);
        unsigned long long v0 = fma2(C2, b1, u0);
        unsigned long long u1 = fma2(NEG1, b1, r.y);
        unsigned long long vn = fma2(C2, v0, u1);
        b2 = v0; b1 = vn;
    }

    // --- finalize both chains into the global frame, sum in-register ---
    const float fcA = f0v * (float)(2 * pair + 1) * inv_sr;
    const float fcB = f0v * (float)(2 * pair + 2) * inv_sr;

    float reA = 0.0f, imA = 0.0f, reB = 0.0f, imB = 0.0f;
    #pragma unroll
    for (int c = 0; c < 2; ++c) {
        float x1A, x1B, x2A, x2B;
        if (c == 0) { upk(a1, x1A, x1B); upk(a2, x2A, x2B); }
        else        { upk(b1, x1A, x1B); upk(b2, x2A, x2B); }
        const float nend = (float)((2 * sp + c) * 64 + 63);
        {
            float yre = fmaf(-cth.x, x2A, x1A);
            float yim = sth.x * x2A;
            float p   = fcA * nend;
            p -= floorf(p);
            float sphi, cphi;
            __sincosf(TWO_PI_F * p, &sphi, &cphi);
            reA += yre * cphi + yim * sphi;
            imA += yim * cphi - yre * sphi;
        }
        {
            float yre = fmaf(-cth.y, x2B, x1B);
            float yim = sth.y * x2B;
            float p   = fcB * nend;
            p -= floorf(p);
            float sphi, cphi;
            __sincosf(TWO_PI_F * p, &sphi, &cphi);
            reB += yre * cphi + yim * sphi;
            imB += yim * cphi - yre * sphi;
        }
    }
    sPart[sp * 64 + 2 * pair]     = make_float2(reA, imA);
    sPart[sp * 64 + 2 * pair + 1] = make_float2(reB, imB);
    __syncthreads();

    // --- single-warp finish: lane l owns harmonics 2l+1, 2l+2 ---
    if (tid < 32) {
        float r0 = 0.0f, i0 = 0.0f, r1 = 0.0f, i1 = 0.0f;
        #pragma unroll
        for (int s = 0; s < 8; ++s) {
            float2 p0 = sPart[s * 64 + 2 * tid];
            float2 p1 = sPart[s * 64 + 2 * tid + 1];
            r0 += p0.x; i0 += p0.y;
            r1 += p1.x; i1 += p1.y;
        }
        float mag0 = sqrtf(r0 * r0 + i0 * i0);
        float mag1 = sqrtf(r1 * r1 + i1 * i1);
        float fch0 = f0v * (float)(2 * tid + 1) * inv_sr;
        float fch1 = f0v * (float)(2 * tid + 2) * inv_sr;
        if (fch0 > 0.5f) mag0 = 0.0f;   // Nyquist mask
        if (fch1 > 0.5f) mag1 = 0.0f;

        float s = mag0 + mag1;
        #pragma unroll
        for (int o = 16; o > 0; o >>= 1)
            s += __shfl_xor_sync(0xffffffffu, s, o);   // amp in all lanes

        float inv = 1.0f / s;
        ((float2*)out_hd)[f * 32 + tid] = make_float2(mag0 * inv, mag1 * inv);
        if (tid == 0)
            out_amp[f] = fminf(fmaxf(s * 2.0f, 0.0f), 1.0f);
    }
}

extern "C" void kernel_launch(void* const* d_in, const int* in_sizes, int n_in,
                              void* d_out, int out_size) {
    const float* audio = (const float*)d_in[0];
    const float* f0    = (const float*)d_in[1];
    const int frames   = in_sizes[1];  // 2*250*1 = 500
    float* out         = (float*)d_out;
    morlet_kernel<<<frames, 256>>>(audio, f0, out, out + (size_t)frames * 64);
}